// round 10
// baseline (speedup 1.0000x reference)
#include <cuda_runtime.h>
#include <cuda_bf16.h>
#include <cstdint>

// DepthToSpace, BLOCK_SIZE=2
// in : x   (B=16, C=256, H=128, W=128) fp32
// out:     (B=16, d=64,  H2=256, W2=256) fp32
//
// out[b, dd, h*2+i, w*2+k] = x[b, (i*2+k)*64 + dd, h, w]
//
// R8: R6's access geometry (dense v8 loads, half-dense v8 stores — best
// measured) converted to a persistent grid-stride kernel sized to exactly
// one resident wave (occupancy-queried at launch; free under graph replay).
// Removes the ~45%-empty tail wave of the 16384-block launch.

#define W_IN      128
#define H_IN      128
#define C_IN      256
#define D_OUT     64
#define CH_STRIDE (H_IN * W_IN)            // 16384 floats per input channel
#define V8_PER_ROW_IN  16                  // 128 in floats per row = 16 v8
#define N_WORK    (16 * D_OUT * 256 * V8_PER_ROW_IN) // 4,194,304 work items
#define BLOCK_T   256

__device__ __forceinline__ void ldg_v8(const float* p, float v[8]) {
    asm volatile(
        "ld.global.v8.b32 {%0,%1,%2,%3,%4,%5,%6,%7}, [%8];"
        : "=f"(v[0]), "=f"(v[1]), "=f"(v[2]), "=f"(v[3]),
          "=f"(v[4]), "=f"(v[5]), "=f"(v[6]), "=f"(v[7])
        : "l"(p));
}

__device__ __forceinline__ void stg_v8(float* p, float a0, float a1, float a2, float a3,
                                                 float a4, float a5, float a6, float a7) {
    asm volatile(
        "st.global.v8.b32 [%0], {%1,%2,%3,%4,%5,%6,%7,%8};"
        :: "l"(p),
           "f"(a0), "f"(a1), "f"(a2), "f"(a3),
           "f"(a4), "f"(a5), "f"(a6), "f"(a7)
        : "memory");
}

__global__ void __launch_bounds__(BLOCK_T)
d2s_kernel(const float* __restrict__ x, float* __restrict__ out) {
    unsigned stride = gridDim.x * BLOCK_T;
    for (unsigned tid = blockIdx.x * BLOCK_T + threadIdx.x; tid < N_WORK; tid += stride) {
        unsigned j   = tid & (V8_PER_ROW_IN - 1); // v8 index within input row (0..15)
        unsigned row = tid >> 4;                  // global output row (0..262143)

        unsigned ho = row & 255;                  // output height index
        unsigned dd = (row >> 8) & (D_OUT - 1);
        unsigned b  = row >> 14;

        unsigned i = ho & 1;
        unsigned h = ho >> 1;

        // float base index into x for (b, c0, h, 0):  c0 = i*128 + dd
        size_t base = (((size_t)b * C_IN + i * 128u + dd) * H_IN + h) * W_IN + 8u * j;

        float a[8], c[8];
        ldg_v8(&x[base], a);                               // c0, w = 8j..8j+7
        ldg_v8(&x[base + (size_t)(64 * CH_STRIDE)], c);    // c1, same w

        // output row `row`, floats 16j..16j+15 = a0,c0,a1,c1,...,a7,c7
        float* o = &out[(size_t)row * 256 + 16u * j];
        stg_v8(o,     a[0], c[0], a[1], c[1], a[2], c[2], a[3], c[3]);
        stg_v8(o + 8, a[4], c[4], a[5], c[5], a[6], c[6], a[7], c[7]);
    }
}

extern "C" void kernel_launch(void* const* d_in, const int* in_sizes, int n_in,
                              void* d_out, int out_size) {
    const float* x   = (const float*)d_in[0];
    float*       out = (float*)d_out;

    // Size the grid to exactly one resident wave. Host-side queries are
    // outside the timed graph-replay path (captured once, replayed).
    int dev = 0, sms = 148, bpm = 6;
    cudaGetDevice(&dev);
    cudaDeviceGetAttribute(&sms, cudaDevAttrMultiProcessorCount, dev);
    cudaOccupancyMaxActiveBlocksPerMultiprocessor(&bpm, d2s_kernel, BLOCK_T, 0);
    if (bpm < 1) bpm = 1;
    int grid = sms * bpm;
    int max_grid = N_WORK / BLOCK_T;          // never launch more blocks than work
    if (grid > max_grid) grid = max_grid;

    d2s_kernel<<<grid, BLOCK_T>>>(x, out);
}